// round 12
// baseline (speedup 1.0000x reference)
#include <cuda_runtime.h>
#include <cuda_bf16.h>
#include <cstdint>

typedef __nv_bfloat16 bf;
#define SEQ  512
#define NTHR 256
#define STG  49152                       // Ahi 16K | Alo 16K | Bhi 8K | Blo 8K
#define REDB (3*STG)
#define SMTOT (3*STG + 24576 + 1280)
#define SW(o) ((o) ^ (((o) >> 4) & 0x70))   // 256B-pitch swizzle

__device__ __align__(1024) bf g_xh[128][65536];
__device__ __align__(1024) bf g_xl[128][65536];
__device__ __align__(1024) bf g_w0h[2048][1152];
__device__ __align__(1024) bf g_w0l[2048][1152];
__device__ __align__(1024) bf g_w1h[2048][2048];
__device__ __align__(1024) bf g_w1l[2048][2048];
__device__ __align__(1024) bf g_hh[2][2][128][1024];
__device__ __align__(1024) bf g_hl[2][2][128][1024];
__device__ float    g_biasP[2][2048];
__device__ unsigned g_flags[128 * 32];

__device__ __forceinline__ uint32_t s2u(const void* p) {
    uint32_t a;
    asm("{ .reg .u64 t; cvta.to.shared.u64 t, %1; cvt.u32.u64 %0, t; }" : "=r"(a) : "l"(p));
    return a;
}
__device__ __forceinline__ void cp16(uint32_t dst, const void* src) {
    asm volatile("cp.async.cg.shared.global [%0], [%1], 16;" :: "r"(dst), "l"(src));
}
__device__ __forceinline__ void cpc() { asm volatile("cp.async.commit_group;"); }
__device__ __forceinline__ void cpw_n(int n) {
    if (n <= 0)      asm volatile("cp.async.wait_group 0;");
    else if (n == 1) asm volatile("cp.async.wait_group 1;");
    else             asm volatile("cp.async.wait_group 2;");
}
__device__ __forceinline__ void ldmx4(unsigned* r, uint32_t a) {
    asm volatile("ldmatrix.sync.aligned.m8n8.x4.shared.b16 {%0,%1,%2,%3}, [%4];"
        : "=r"(r[0]), "=r"(r[1]), "=r"(r[2]), "=r"(r[3]) : "r"(a));
}
__device__ __forceinline__ void mma(float* c, const unsigned* a, const unsigned* b) {
    asm volatile("mma.sync.aligned.m16n8k16.row.col.f32.bf16.bf16.f32 "
        "{%0,%1,%2,%3}, {%4,%5,%6,%7}, {%8,%9}, {%0,%1,%2,%3};"
        : "+f"(c[0]), "+f"(c[1]), "+f"(c[2]), "+f"(c[3])
        : "r"(a[0]), "r"(a[1]), "r"(a[2]), "r"(a[3]), "r"(b[0]), "r"(b[1]));
}
__device__ __forceinline__ void gbar(unsigned& gen) {
    gen++;
    __syncthreads();
    if (threadIdx.x == 0)
        asm volatile("st.release.gpu.global.u32 [%0], %1;"
                     :: "l"(&g_flags[blockIdx.x * 32]), "r"(gen) : "memory");
    if (threadIdx.x < 128) {
        const unsigned* f = &g_flags[threadIdx.x * 32];
        unsigned v;
        do {
            asm volatile("ld.acquire.gpu.global.u32 %0, [%1];" : "=r"(v) : "l"(f) : "memory");
            if (v < gen) __nanosleep(32);
        } while (v < gen);
    }
    __syncthreads();
}

__global__ void __launch_bounds__(NTHR, 1) gru_mma(
    const float* __restrict__ Wfc, const float* __restrict__ bfc,
    float* __restrict__ out) {
    extern __shared__ __align__(1024) char sm[];
    const uint32_t sb = s2u(sm);
    const int tid = threadIdx.x, warp = tid >> 5, lane = tid & 31;
    const int ctan = blockIdx.x & 63, ctam = blockIdx.x >> 6;
    float* redK  = (float*)(sm + REDB);            // 6 warps x 32 lanes x 32 f
    float* sbias = (float*)(sm + REDB + 24576);
    float* sred  = sbias + 64;
    if (tid < 64) sbias[tid] = g_biasP[tid >> 5][ctan * 32 + (tid & 31)];
    __syncthreads();

    const int mh = warp & 1;            // m-half (32 rows)
    const int kq = warp >> 1;           // k-quarter (32 elems = 64 bytes)
    const uint32_t aoff0 = (mh * 32 + (lane & 15)) * 256 + (lane >> 4) * 16 + kq * 64;
    const uint32_t aoff1 = aoff0 + 16 * 256;
    const uint32_t boff0 = (((lane >> 4) & 1) * 8 + (lane & 7)) * 256 + ((lane >> 3) & 1) * 16 + kq * 64;
    const uint32_t boff1 = boff0 + 16 * 256;
    unsigned gen = 0; int p = 0;
    int pcnt = 0, ccnt = 0;
    float acc0[4][4], acc1[4][4];

    auto stageF = [&](int lay, int tt, int pp, int c) {
        const bf *ah, *al; long rstr; int ko;
        if (!lay) {
            if (c == 0) { ah = &g_xh[0][0]; al = &g_xl[0][0]; rstr = 65536; ko = tt * 128; }
            else { ah = &g_hh[0][pp][0][0]; al = &g_hl[0][pp][0][0]; rstr = 1024; ko = (c - 1) * 128; }
        } else {
            if (c < 8) { ah = &g_hh[0][pp ^ 1][0][0]; al = &g_hl[0][pp ^ 1][0][0]; rstr = 1024; ko = c * 128; }
            else { ah = &g_hh[1][pp][0][0]; al = &g_hl[1][pp][0][0]; rstr = 1024; ko = (c - 8) * 128; }
        }
        const bf* wh = lay ? &g_w1h[0][0] : &g_w0h[0][0];
        const bf* wl = lay ? &g_w1l[0][0] : &g_w0l[0][0];
        const long Kst = lay ? 2048 : 1152;
        uint32_t db = sb + (pcnt % 3) * STG;
        #pragma unroll
        for (int it = 0; it < 8; it++) {                 // A: 64r x 16u x 2d
            int idx = it * NTHR + tid, d = idx >> 10, r = (idx >> 4) & 63, u = idx & 15;
            cp16(db + d * 16384 + SW(r * 256 + u * 16),
                 (d ? al : ah) + (long)(ctam * 64 + r) * rstr + ko + u * 8);
        }
        #pragma unroll
        for (int it = 0; it < 4; it++) {                 // B: 32r x 16u x 2d
            int idx = it * NTHR + tid, d = idx >> 9, r = (idx >> 4) & 31, u = idx & 15;
            cp16(db + 32768 + d * 8192 + SW(r * 256 + u * 16),
                 (d ? wl : wh) + (long)(ctan * 32 + r) * Kst + c * 128 + u * 8);
        }
        cpc(); pcnt++;
    };

    auto computeC = [&]() {
        uint32_t tb = sb + (ccnt % 3) * STG;
        #pragma unroll
        for (int kk = 0; kk < 2; kk++) {
            const uint32_t kb = kk * 32;
            unsigned a0[4], a1[4], l0[4], l1[4], bh[8], bl[8];
            ldmx4(a0, tb + SW(aoff0 + kb));
            ldmx4(a1, tb + SW(aoff1 + kb));
            ldmx4(l0, tb + 16384 + SW(aoff0 + kb));
            ldmx4(l1, tb + 16384 + SW(aoff1 + kb));
            ldmx4(bh,     tb + 32768 + SW(boff0 + kb));
            ldmx4(bh + 4, tb + 32768 + SW(boff1 + kb));
            ldmx4(bl,     tb + 40960 + SW(boff0 + kb));
            ldmx4(bl + 4, tb + 40960 + SW(boff1 + kb));
            #pragma unroll
            for (int j = 0; j < 4; j++) { mma(acc0[j], a0, bh + 2 * j); mma(acc1[j], a1, bh + 2 * j); }
            #pragma unroll
            for (int j = 0; j < 4; j++) { mma(acc0[j], a0, bl + 2 * j); mma(acc1[j], a1, bl + 2 * j); }
            #pragma unroll
            for (int j = 0; j < 4; j++) { mma(acc0[j], l0, bh + 2 * j); mma(acc1[j], l1, bh + 2 * j); }
        }
        ccnt++;
    };

    auto epi = [&](int lay) {
        __syncthreads();
        if (kq != 0) {
            float4* rb = (float4*)redK + (((kq - 1) * 2 + mh) * 32 + lane) * 8;
            #pragma unroll
            for (int j = 0; j < 4; j++) {
                rb[j]     = make_float4(acc0[j][0], acc0[j][1], acc0[j][2], acc0[j][3]);
                rb[j + 4] = make_float4(acc1[j][0], acc1[j][1], acc1[j][2], acc1[j][3]);
            }
        }
        __syncthreads();
        if (kq == 0) {
            #pragma unroll
            for (int w = 0; w < 3; w++) {
                const float4* rb = (const float4*)redK + ((w * 2 + mh) * 32 + lane) * 8;
                #pragma unroll
                for (int j = 0; j < 4; j++) {
                    float4 v = rb[j];
                    acc0[j][0] += v.x; acc0[j][1] += v.y; acc0[j][2] += v.z; acc0[j][3] += v.w;
                    v = rb[j + 4];
                    acc1[j][0] += v.x; acc1[j][1] += v.y; acc1[j][2] += v.z; acc1[j][3] += v.w;
                }
            }
            bf* hh = &g_hh[lay][p ^ 1][0][0];  bf* hl = &g_hl[lay][p ^ 1][0][0];
            const bf* qh = &g_hh[lay][p][0][0]; const bf* ql = &g_hl[lay][p][0][0];
            #pragma unroll
            for (int mt = 0; mt < 2; mt++) {
                float (*ac)[4] = mt ? acc1 : acc0;
                const int r0 = ctam * 64 + mh * 32 + mt * 16 + (lane >> 2);
                #pragma unroll
                for (int j = 0; j < 4; j++) {
                    int ul = j * 4 + (lane & 3);
                    int ug = ctan * 16 + ul;
                    float bz = sbias[lay * 32 + 2 * ul], bn = sbias[lay * 32 + 2 * ul + 1];
                    #pragma unroll
                    for (int rr = 0; rr < 2; rr++) {
                        int r = r0 + rr * 8;
                        float z = 1.f / (1.f + __expf(-(ac[j][rr * 2] + bz)));
                        float e = __expf(2.f * (ac[j][rr * 2 + 1] + bn));
                        float nn = __fdividef(e - 1.f, e + 1.f);
                        float hp = __bfloat162float(qh[r * 1024 + ug]) + __bfloat162float(ql[r * 1024 + ug]);
                        float hv = (1.f - z) * nn + z * hp;
                        bf hi = __float2bfloat16(hv);
                        hh[r * 1024 + ug] = hi;
                        hl[r * 1024 + ug] = __float2bfloat16(hv - __bfloat162float(hi));
                    }
                }
            }
        }
        __syncthreads();
    };

    stageF(0, 0, 0, 0); stageF(0, 0, 0, 1);

    for (int t = 0; t < SEQ; t++) {
        #pragma unroll
        for (int j = 0; j < 4; j++)
            #pragma unroll
            for (int e = 0; e < 4; e++) { acc0[j][e] = 0.f; acc1[j][e] = 0.f; }
        for (int c = 0; c < 9; c++) {
            cpw_n(pcnt - ccnt - 1);
            __syncthreads();
            if (c + 2 < 9) stageF(0, t, p, c + 2);
            computeC();
        }
        epi(0);
        gbar(gen);
        stageF(1, t, p, 0); stageF(1, t, p, 1);
        #pragma unroll
        for (int j = 0; j < 4; j++)
            #pragma unroll
            for (int e = 0; e < 4; e++) { acc0[j][e] = 0.f; acc1[j][e] = 0.f; }
        for (int c = 0; c < 16; c++) {
            cpw_n(pcnt - ccnt - 1);
            __syncthreads();
            if (c + 2 < 16) stageF(1, t, p, c + 2);
            else if (t + 1 < SEQ) stageF(0, t + 1, p ^ 1, c + 2 - 16);
            computeC();
        }
        epi(1);
        p ^= 1;
    }
    gbar(gen);

    const bf* fh = &g_hh[1][p][0][0];
    const bf* fl = &g_hl[1][p][0][0];
    const int row = blockIdx.x;
    float part = 0.f;
    for (int j = tid; j < 1024; j += NTHR)
        part += (__bfloat162float(fh[row * 1024 + j]) + __bfloat162float(fl[row * 1024 + j])) * Wfc[j];
    sred[tid] = part;
    __syncthreads();
    if (tid == 0) {
        float s = 0.f;
        #pragma unroll 8
        for (int i = 0; i < NTHR; i++) s += sred[i];
        out[row] = s + bfc[0];
    }
}

__global__ void ginit(const float* __restrict__ x,
                      const float* __restrict__ b0, const float* __restrict__ b1) {
    long i = (long)blockIdx.x * blockDim.x + threadIdx.x;
    long st = (long)gridDim.x * blockDim.x;
    for (long idx = i; idx < 128L * 65536; idx += st) {
        float v = x[idx];
        bf h = __float2bfloat16(v);
        ((bf*)g_xh)[idx] = h;
        ((bf*)g_xl)[idx] = __float2bfloat16(v - __bfloat162float(h));
    }
    bf z = __float2bfloat16(0.f);
    for (long idx = i; idx < 2L * 2 * 128 * 1024; idx += st) {
        ((bf*)g_hh)[idx] = z; ((bf*)g_hl)[idx] = z;
    }
    if (i < 128 * 32) g_flags[i] = 0u;
    if (i < 4096) {
        int l = (int)(i >> 11), g = (int)(i & 2047);
        int u = g >> 1, col = (g & 1) ? 2048 + u : u;
        g_biasP[l][g] = l ? b1[col] : b0[col];
    }
}

__global__ void prepw(const float* __restrict__ W0, const float* __restrict__ W1) {
    const int l = blockIdx.z;
    const float* W = l ? W1 : W0;
    bf* Dh = l ? &g_w1h[0][0] : &g_w0h[0][0];
    bf* Dl = l ? &g_w1l[0][0] : &g_w0l[0][0];
    const int K = l ? 2048 : 1152;
    const int k0 = blockIdx.x * 32; if (k0 >= K) return;
    const int g0 = blockIdx.y * 32;
    __shared__ float tile[32][33];
    const int tx = threadIdx.x, ty = threadIdx.y;
    {
        int g = g0 + tx, u = g >> 1, col = (g & 1) ? 2048 + u : u;
        #pragma unroll
        for (int r = 0; r < 32; r += 8)
            tile[ty + r][tx] = W[(size_t)(k0 + ty + r) * 3072 + col];
    }
    __syncthreads();
    #pragma unroll
    for (int r = 0; r < 32; r += 8) {
        float v = tile[tx][ty + r];
        bf h = __float2bfloat16(v);
        size_t o = (size_t)(g0 + ty + r) * K + k0 + tx;
        Dh[o] = h;
        Dl[o] = __float2bfloat16(v - __bfloat162float(h));
    }
}

extern "C" void kernel_launch(void* const* d_in, const int* in_sizes, int n_in,
                              void* d_out, int out_size) {
    const float* x   = (const float*)d_in[0];
    const float* W0  = (const float*)d_in[1];
    const float* b0  = (const float*)d_in[2];
    const float* W1  = (const float*)d_in[3];
    const float* b1  = (const float*)d_in[4];
    const float* Wfc = (const float*)d_in[5];
    const float* bfc = (const float*)d_in[6];
    float* out = (float*)d_out;

    cudaFuncSetAttribute(gru_mma, cudaFuncAttributeMaxDynamicSharedMemorySize, SMTOT);
    ginit<<<2048, 256>>>(x, b0, b1);
    prepw<<<dim3(64, 64, 2), dim3(32, 8)>>>(W0, W1);
    gru_mma<<<128, NTHR, SMTOT>>>(Wfc, bfc, out);
}

// round 13
// speedup vs baseline: 1.2809x; 1.2809x over previous
#include <cuda_runtime.h>
#include <cuda_bf16.h>
#include <cstdint>

typedef __nv_bfloat16 bf;
#define SEQ  512
#define NTHR 128
#define STG  16384                        // Ahi 4K | Alo 4K | Bhi 4K | Blo 4K
#define SMTOT (4*STG + 4096 + 256 + 512)
#define SW(o) ((o) ^ (((o) >> 3) & 0x70))

__device__ __align__(1024) bf g_xh[128][65536];
__device__ __align__(1024) bf g_xl[128][65536];
__device__ __align__(1024) bf g_w0h[2048][1152];
__device__ __align__(1024) bf g_w0l[2048][1152];
__device__ __align__(1024) bf g_w1h[2048][2048];
__device__ __align__(1024) bf g_w1l[2048][2048];
__device__ __align__(1024) bf g_hh[2][2][128][1024];   // [layer][ping][row][unit]
__device__ __align__(1024) bf g_hl[2][2][128][1024];
__device__ float    g_biasP[2][2048];
__device__ unsigned g_flags[256 * 32];

__device__ __forceinline__ uint32_t s2u(const void* p) {
    uint32_t a;
    asm("{ .reg .u64 t; cvta.to.shared.u64 t, %1; cvt.u32.u64 %0, t; }" : "=r"(a) : "l"(p));
    return a;
}
__device__ __forceinline__ void cp16(uint32_t dst, const void* src) {
    asm volatile("cp.async.cg.shared.global [%0], [%1], 16;" :: "r"(dst), "l"(src));
}
__device__ __forceinline__ void cpc() { asm volatile("cp.async.commit_group;"); }
__device__ __forceinline__ void cpw_n(int n) {
    if (n <= 0)      asm volatile("cp.async.wait_group 0;");
    else if (n == 1) asm volatile("cp.async.wait_group 1;");
    else             asm volatile("cp.async.wait_group 2;");
}
__device__ __forceinline__ void ldmx4(unsigned* r, uint32_t a) {
    asm volatile("ldmatrix.sync.aligned.m8n8.x4.shared.b16 {%0,%1,%2,%3}, [%4];"
        : "=r"(r[0]), "=r"(r[1]), "=r"(r[2]), "=r"(r[3]) : "r"(a));
}
__device__ __forceinline__ void mma(float* c, const unsigned* a, const unsigned* b) {
    asm volatile("mma.sync.aligned.m16n8k16.row.col.f32.bf16.bf16.f32 "
        "{%0,%1,%2,%3}, {%4,%5,%6,%7}, {%8,%9}, {%0,%1,%2,%3};"
        : "+f"(c[0]), "+f"(c[1]), "+f"(c[2]), "+f"(c[3])
        : "r"(a[0]), "r"(a[1]), "r"(a[2]), "r"(a[3]), "r"(b[0]), "r"(b[1]));
}
__device__ __forceinline__ void gbar(unsigned& gen) {
    gen++;
    __syncthreads();
    if (threadIdx.x == 0)
        asm volatile("st.release.gpu.global.u32 [%0], %1;"
                     :: "l"(&g_flags[blockIdx.x * 32]), "r"(gen) : "memory");
    {   // 128 threads watch 256 flags (2 each)
        const unsigned* f0 = &g_flags[threadIdx.x * 32];
        const unsigned* f1 = &g_flags[(threadIdx.x + 128) * 32];
        unsigned v0, v1;
        do {
            asm volatile("ld.acquire.gpu.global.u32 %0, [%1];" : "=r"(v0) : "l"(f0) : "memory");
            asm volatile("ld.acquire.gpu.global.u32 %0, [%1];" : "=r"(v1) : "l"(f1) : "memory");
            if (v0 < gen || v1 < gen) __nanosleep(32);
        } while (v0 < gen || v1 < gen);
    }
    __syncthreads();
}

__global__ void __launch_bounds__(NTHR, 2) gru_mma(
    const float* __restrict__ Wfc, const float* __restrict__ bfc,
    float* __restrict__ out) {
    extern __shared__ __align__(1024) char sm[];
    const uint32_t sb = s2u(sm);
    const int tid = threadIdx.x, warp = tid >> 5, lane = tid & 31;
    const int ctan = blockIdx.x & 63, ctam = blockIdx.x >> 6;   // 64 n-slices x 4 m-quarters
    float* redK  = (float*)(sm + 4 * STG);          // 2 warps x 32 lanes x 16 f = 4KB
    float* sbias = (float*)(sm + 4 * STG + 4096);
    float* sred  = sbias + 64;
    if (tid < 64) sbias[tid] = g_biasP[tid >> 5][ctan * 32 + (tid & 31)];
    __syncthreads();

    const int wm = warp & 1;            // m-half (16 rows)
    const int kh = warp >> 1;           // k-half (32 of KC=64)
    const uint32_t aoff  = (wm * 16 + (lane & 15)) * 128 + (lane >> 4) * 16;
    const uint32_t boff0 = (((lane >> 4) & 1) * 8 + (lane & 7)) * 128 + ((lane >> 3) & 1) * 16;
    const uint32_t boff1 = boff0 + 16 * 128;
    unsigned gen = 0; int p = 0;
    int pcnt = 0, ccnt = 0;
    float acc[4][4];

    auto stageF = [&](int lay, int tt, int pp, int c) {
        const bf *ah, *al; long rstr; int ko;
        if (!lay) {
            if (c < 2) { ah = &g_xh[0][0]; al = &g_xl[0][0]; rstr = 65536; ko = tt * 128 + c * 64; }
            else { ah = &g_hh[0][pp][0][0]; al = &g_hl[0][pp][0][0]; rstr = 1024; ko = (c - 2) * 64; }
        } else {
            if (c < 16) { ah = &g_hh[0][pp ^ 1][0][0]; al = &g_hl[0][pp ^ 1][0][0]; rstr = 1024; ko = c * 64; }
            else { ah = &g_hh[1][pp][0][0]; al = &g_hl[1][pp][0][0]; rstr = 1024; ko = (c - 16) * 64; }
        }
        const bf* wh = lay ? &g_w1h[0][0] : &g_w0h[0][0];
        const bf* wl = lay ? &g_w1l[0][0] : &g_w0l[0][0];
        const long Kst = lay ? 2048 : 1152;
        uint32_t db = sb + (pcnt & 3) * STG;
        #pragma unroll
        for (int it = 0; it < 4; it++) {                 // A: 32r x 8u x 2(hi/lo)
            int idx = it * NTHR + tid, d = idx >> 8, r = (idx >> 3) & 31, u = idx & 7;
            cp16(db + d * 4096 + SW(r * 128 + u * 16),
                 (d ? al : ah) + (long)(ctam * 32 + r) * rstr + ko + u * 8);
        }
        #pragma unroll
        for (int it = 0; it < 4; it++) {                 // B: 32r x 8u x 2
            int idx = it * NTHR + tid, d = idx >> 8, r = (idx >> 3) & 31, u = idx & 7;
            cp16(db + 8192 + d * 4096 + SW(r * 128 + u * 16),
                 (d ? wl : wh) + (long)(ctan * 32 + r) * Kst + c * 64 + u * 8);
        }
        cpc(); pcnt++;
    };

    auto computeC = [&]() {
        uint32_t tb = sb + (ccnt & 3) * STG;
        #pragma unroll
        for (int kk = 0; kk < 2; kk++) {
            const uint32_t ko = kh * 64 + kk * 32;
            unsigned ah[4], al[4], bh[8], bl[8];
            ldmx4(ah, tb + SW(aoff + ko));
            ldmx4(al, tb + 4096 + SW(aoff + ko));
            ldmx4(bh,     tb + 8192 + SW(boff0 + ko));
            ldmx4(bh + 4, tb + 8192 + SW(boff1 + ko));
            ldmx4(bl,     tb + 12288 + SW(boff0 + ko));
            ldmx4(bl + 4, tb + 12288 + SW(boff1 + ko));
            #pragma unroll
            for (int j = 0; j < 4; j++) mma(acc[j], ah, bh + 2 * j);
            #pragma unroll
            for (int j = 0; j < 4; j++) mma(acc[j], ah, bl + 2 * j);
            #pragma unroll
            for (int j = 0; j < 4; j++) mma(acc[j], al, bh + 2 * j);
        }
        ccnt++;
    };

    auto epi = [&](int lay) {
        __syncthreads();
        if (kh == 1) {
            float4* rb = (float4*)redK + (wm * 32 + lane) * 4;
            #pragma unroll
            for (int j = 0; j < 4; j++)
                rb[j] = make_float4(acc[j][0], acc[j][1], acc[j][2], acc[j][3]);
        }
        __syncthreads();
        if (kh == 0) {
            const float4* rb = (const float4*)redK + (wm * 32 + lane) * 4;
            #pragma unroll
            for (int j = 0; j < 4; j++) {
                float4 v = rb[j];
                acc[j][0] += v.x; acc[j][1] += v.y; acc[j][2] += v.z; acc[j][3] += v.w;
            }
            bf* hh = &g_hh[lay][p ^ 1][0][0];  bf* hl = &g_hl[lay][p ^ 1][0][0];
            const bf* qh = &g_hh[lay][p][0][0]; const bf* ql = &g_hl[lay][p][0][0];
            const int r0 = ctam * 32 + wm * 16 + (lane >> 2);
            #pragma unroll
            for (int j = 0; j < 4; j++) {
                int ul = j * 4 + (lane & 3);
                int ug = ctan * 16 + ul;
                float bz = sbias[lay * 32 + 2 * ul], bn = sbias[lay * 32 + 2 * ul + 1];
                #pragma unroll
                for (int rr = 0; rr < 2; rr++) {
                    int r = r0 + rr * 8;
                    float z = 1.f / (1.f + __expf(-(acc[j][rr * 2] + bz)));
                    float e = __expf(2.f * (acc[j][rr * 2 + 1] + bn));
                    float nn = __fdividef(e - 1.f, e + 1.f);
                    float hp = __bfloat162float(qh[r * 1024 + ug]) + __bfloat162float(ql[r * 1024 + ug]);
                    float hv = (1.f - z) * nn + z * hp;
                    bf hi = __float2bfloat16(hv);
                    hh[r * 1024 + ug] = hi;
                    hl[r * 1024 + ug] = __float2bfloat16(hv - __bfloat162float(hi));
                }
            }
        }
        __syncthreads();
    };

    stageF(0, 0, 0, 0); stageF(0, 0, 0, 1); stageF(0, 0, 0, 2);

    for (int t = 0; t < SEQ; t++) {
        #pragma unroll
        for (int j = 0; j < 4; j++) acc[j][0]=acc[j][1]=acc[j][2]=acc[j][3]=0.f;
        for (int c = 0; c < 18; c++) {
            cpw_n(pcnt - ccnt - 1);
            __syncthreads();
            if (c + 3 < 18) stageF(0, t, p, c + 3);
            computeC();
        }
        epi(0);
        gbar(gen);
        stageF(1, t, p, 0); stageF(1, t, p, 1); stageF(1, t, p, 2);
        #pragma unroll
        for (int j = 0; j < 4; j++) acc[j][0]=acc[j][1]=acc[j][2]=acc[j][3]=0.f;
        for (int c = 0; c < 32; c++) {
            cpw_n(pcnt - ccnt - 1);
            __syncthreads();
            if (c + 3 < 32) stageF(1, t, p, c + 3);
            else if (t + 1 < SEQ) stageF(0, t + 1, p ^ 1, c + 3 - 32);
            computeC();
        }
        epi(1);
        p ^= 1;
    }
    gbar(gen);

    if (blockIdx.x < 128) {
        const bf* fh = &g_hh[1][p][0][0];
        const bf* fl = &g_hl[1][p][0][0];
        const int row = blockIdx.x;
        float part = 0.f;
        for (int j = tid; j < 1024; j += NTHR)
            part += (__bfloat162float(fh[row * 1024 + j]) + __bfloat162float(fl[row * 1024 + j])) * Wfc[j];
        sred[tid] = part;
        __syncthreads();
        if (tid == 0) {
            float s = 0.f;
            #pragma unroll 8
            for (int i = 0; i < NTHR; i++) s += sred[i];
            out[row] = s + bfc[0];
        }
    }
}

__global__ void ginit(const float* __restrict__ x,
                      const float* __restrict__ b0, const float* __restrict__ b1) {
    long i = (long)blockIdx.x * blockDim.x + threadIdx.x;
    long st = (long)gridDim.x * blockDim.x;
    for (long idx = i; idx < 128L * 65536; idx += st) {
        float v = x[idx];
        bf h = __float2bfloat16(v);
        ((bf*)g_xh)[idx] = h;
        ((bf*)g_xl)[idx] = __float2bfloat16(v - __bfloat162float(h));
    }
    bf z = __float2bfloat16(0.f);
    for (long idx = i; idx < 2L * 2 * 128 * 1024; idx += st) {
        ((bf*)g_hh)[idx] = z; ((bf*)g_hl)[idx] = z;
    }
    if (i < 256 * 32) g_flags[i] = 0u;
    if (i < 4096) {
        int l = (int)(i >> 11), g = (int)(i & 2047);
        int u = g >> 1, col = (g & 1) ? 2048 + u : u;
        g_biasP[l][g] = l ? b1[col] : b0[col];
    }
}

__global__ void prepw(const float* __restrict__ W0, const float* __restrict__ W1) {
    const int l = blockIdx.z;
    const float* W = l ? W1 : W0;
    bf* Dh = l ? &g_w1h[0][0] : &g_w0h[0][0];
    bf* Dl = l ? &g_w1l[0][0] : &g_w0l[0][0];
    const int K = l ? 2048 : 1152;
    const int k0 = blockIdx.x * 32; if (k0 >= K) return;
    const int g0 = blockIdx.y * 32;
    __shared__ float tile[32][33];
    const int tx = threadIdx.x, ty = threadIdx.y;
    {
        int g = g0 + tx, u = g >> 1, col = (g & 1) ? 2048 + u : u;
        #pragma unroll
        for (int r = 0; r < 32; r += 8)
            tile[ty + r][tx] = W[(size_t)(k0 + ty + r) * 3072 + col];
    }
    __syncthreads();
    #pragma unroll
    for (int r = 0; r < 32; r += 8) {
        float v = tile[tx][ty + r];
        bf h = __float2bfloat16(v);
        size_t o = (size_t)(g0 + ty + r) * K + k0 + tx;
        Dh[o] = h;
        Dl[o] = __float2bfloat16(v - __bfloat162float(h));
    }
}

extern "C" void kernel_launch(void* const* d_in, const int* in_sizes, int n_in,
                              void* d_out, int out_size) {
    const float* x   = (const float*)d_in[0];
    const float* W0  = (const float*)d_in[1];
    const float* b0  = (const float*)d_in[2];
    const float* W1  = (const float*)d_in[3];
    const float* b1  = (const float*)d_in[4];
    const float* Wfc = (const float*)d_in[5];
    const float* bfc = (const float*)d_in[6];
    float* out = (float*)d_out;

    cudaFuncSetAttribute(gru_mma, cudaFuncAttributeMaxDynamicSharedMemorySize, SMTOT);
    ginit<<<2048, 256>>>(x, b0, b1);
    prepw<<<dim3(64, 64, 2), dim3(32, 8)>>>(W0, W1);
    gru_mma<<<256, NTHR, SMTOT>>>(Wfc, bfc, out);
}

// round 14
// speedup vs baseline: 1.2893x; 1.0066x over previous
#include <cuda_runtime.h>
#include <cuda_bf16.h>
#include <cstdint>

typedef __nv_bfloat16 bf;
#define SEQ  512
#define NTHR 128
#define STG  16384                        // Ahi 4K | Alo 4K | Bhi 4K | Blo 4K
#define SMTOT (4*STG + 4096 + 256 + 512)
#define SW(o) ((o) ^ (((o) >> 3) & 0x70))

__device__ __align__(1024) bf g_xh[128][65536];
__device__ __align__(1024) bf g_xl[128][65536];
__device__ __align__(1024) bf g_w0h[2048][1152];
__device__ __align__(1024) bf g_w0l[2048][1152];
__device__ __align__(1024) bf g_w1h[2048][2048];
__device__ __align__(1024) bf g_w1l[2048][2048];
__device__ __align__(1024) bf g_hh[2][2][128][1024];   // [layer][ping][row][unit]
__device__ __align__(1024) bf g_hl[2][2][128][1024];
__device__ float    g_biasP[2][2048];
__device__ unsigned g_flagsA[256 * 32];
__device__ unsigned g_flagsB[256 * 32];

__device__ __forceinline__ uint32_t s2u(const void* p) {
    uint32_t a;
    asm("{ .reg .u64 t; cvta.to.shared.u64 t, %1; cvt.u32.u64 %0, t; }" : "=r"(a) : "l"(p));
    return a;
}
__device__ __forceinline__ void cp16(uint32_t dst, const void* src) {
    asm volatile("cp.async.cg.shared.global [%0], [%1], 16;" :: "r"(dst), "l"(src));
}
__device__ __forceinline__ void cpc() { asm volatile("cp.async.commit_group;"); }
__device__ __forceinline__ void cpw_n(int n) {
    if (n <= 0)      asm volatile("cp.async.wait_group 0;");
    else if (n == 1) asm volatile("cp.async.wait_group 1;");
    else             asm volatile("cp.async.wait_group 2;");
}
__device__ __forceinline__ void ldmx4(unsigned* r, uint32_t a) {
    asm volatile("ldmatrix.sync.aligned.m8n8.x4.shared.b16 {%0,%1,%2,%3}, [%4];"
        : "=r"(r[0]), "=r"(r[1]), "=r"(r[2]), "=r"(r[3]) : "r"(a));
}
__device__ __forceinline__ void mma(float* c, const unsigned* a, const unsigned* b) {
    asm volatile("mma.sync.aligned.m16n8k16.row.col.f32.bf16.bf16.f32 "
        "{%0,%1,%2,%3}, {%4,%5,%6,%7}, {%8,%9}, {%0,%1,%2,%3};"
        : "+f"(c[0]), "+f"(c[1]), "+f"(c[2]), "+f"(c[3])
        : "r"(a[0]), "r"(a[1]), "r"(a[2]), "r"(a[3]), "r"(b[0]), "r"(b[1]));
}
// arrive: caller guarantees a preceding __syncthreads (epi ends with one)
__device__ __forceinline__ void arrive(unsigned* flags, unsigned& gen) {
    gen++;
    if (threadIdx.x == 0)
        asm volatile("st.release.gpu.global.u32 [%0], %1;"
                     :: "l"(&flags[blockIdx.x * 32]), "r"(gen) : "memory");
}
__device__ __forceinline__ void waitf(const unsigned* flags, unsigned gen) {
    const unsigned* f0 = &flags[threadIdx.x * 32];
    const unsigned* f1 = &flags[(threadIdx.x + 128) * 32];
    unsigned v0, v1;
    do {
        asm volatile("ld.acquire.gpu.global.u32 %0, [%1];" : "=r"(v0) : "l"(f0) : "memory");
        asm volatile("ld.acquire.gpu.global.u32 %0, [%1];" : "=r"(v1) : "l"(f1) : "memory");
        if (v0 < gen || v1 < gen) __nanosleep(32);
    } while (v0 < gen || v1 < gen);
    __syncthreads();
}

__global__ void __launch_bounds__(NTHR, 2) gru_mma(
    const float* __restrict__ Wfc, const float* __restrict__ bfc,
    float* __restrict__ out) {
    extern __shared__ __align__(1024) char sm[];
    const uint32_t sb = s2u(sm);
    const int tid = threadIdx.x, warp = tid >> 5, lane = tid & 31;
    const int ctan = blockIdx.x & 63, ctam = blockIdx.x >> 6;   // 64 n x 4 m
    float* redK  = (float*)(sm + 4 * STG);
    float* sbias = (float*)(sm + 4 * STG + 4096);
    float* sred  = sbias + 64;
    if (tid < 64) sbias[tid] = g_biasP[tid >> 5][ctan * 32 + (tid & 31)];
    __syncthreads();

    const int wm = warp & 1;            // m-half (16 rows)
    const int kh = warp >> 1;           // k-half (32 of KC=64)
    const uint32_t aoff  = (wm * 16 + (lane & 15)) * 128 + (lane >> 4) * 16;
    const uint32_t boff0 = (((lane >> 4) & 1) * 8 + (lane & 7)) * 128 + ((lane >> 3) & 1) * 16;
    const uint32_t boff1 = boff0 + 16 * 128;
    unsigned genA = 0, genB = 0; int p = 0;
    int pcnt = 0, ccnt = 0;
    float acc[4][4];

    // orig chunk index semantics: L0: c<2 -> x, else h0_prev. L1: c<16 -> h0_new, else h1_prev.
    auto stageF = [&](int lay, int tt, int pp, int c) {
        const bf *ah, *al; long rstr; int ko;
        if (!lay) {
            if (c < 2) { ah = &g_xh[0][0]; al = &g_xl[0][0]; rstr = 65536; ko = tt * 128 + c * 64; }
            else { ah = &g_hh[0][pp][0][0]; al = &g_hl[0][pp][0][0]; rstr = 1024; ko = (c - 2) * 64; }
        } else {
            if (c < 16) { ah = &g_hh[0][pp ^ 1][0][0]; al = &g_hl[0][pp ^ 1][0][0]; rstr = 1024; ko = c * 64; }
            else { ah = &g_hh[1][pp][0][0]; al = &g_hl[1][pp][0][0]; rstr = 1024; ko = (c - 16) * 64; }
        }
        const bf* wh = lay ? &g_w1h[0][0] : &g_w0h[0][0];
        const bf* wl = lay ? &g_w1l[0][0] : &g_w0l[0][0];
        const long Kst = lay ? 2048 : 1152;
        uint32_t db = sb + (pcnt & 3) * STG;
        #pragma unroll
        for (int it = 0; it < 4; it++) {
            int idx = it * NTHR + tid, d = idx >> 8, r = (idx >> 3) & 31, u = idx & 7;
            cp16(db + d * 4096 + SW(r * 128 + u * 16),
                 (d ? al : ah) + (long)(ctam * 32 + r) * rstr + ko + u * 8);
        }
        #pragma unroll
        for (int it = 0; it < 4; it++) {
            int idx = it * NTHR + tid, d = idx >> 8, r = (idx >> 3) & 31, u = idx & 7;
            cp16(db + 8192 + d * 4096 + SW(r * 128 + u * 16),
                 (d ? wl : wh) + (long)(ctan * 32 + r) * Kst + c * 64 + u * 8);
        }
        cpc(); pcnt++;
    };

    auto computeC = [&]() {
        uint32_t tb = sb + (ccnt & 3) * STG;
        #pragma unroll
        for (int kk = 0; kk < 2; kk++) {
            const uint32_t ko = kh * 64 + kk * 32;
            unsigned ah[4], al[4], bh[8], bl[8];
            ldmx4(ah, tb + SW(aoff + ko));
            ldmx4(al, tb + 4096 + SW(aoff + ko));
            ldmx4(bh,     tb + 8192 + SW(boff0 + ko));
            ldmx4(bh + 4, tb + 8192 + SW(boff1 + ko));
            ldmx4(bl,     tb + 12288 + SW(boff0 + ko));
            ldmx4(bl + 4, tb + 12288 + SW(boff1 + ko));
            #pragma unroll
            for (int j = 0; j < 4; j++) mma(acc[j], ah, bh + 2 * j);
            #pragma unroll
            for (int j = 0; j < 4; j++) mma(acc[j], ah, bl + 2 * j);
            #pragma unroll
            for (int j = 0; j < 4; j++) mma(acc[j], al, bh + 2 * j);
        }
        ccnt++;
    };

    auto epi = [&](int lay) {
        __syncthreads();
        if (kh == 1) {
            float4* rb = (float4*)redK + (wm * 32 + lane) * 4;
            #pragma unroll
            for (int j = 0; j < 4; j++)
                rb[j] = make_float4(acc[j][0], acc[j][1], acc[j][2], acc[j][3]);
        }
        __syncthreads();
        if (kh == 0) {
            const float4* rb = (const float4*)redK + (wm * 32 + lane) * 4;
            #pragma unroll
            for (int j = 0; j < 4; j++) {
                float4 v = rb[j];
                acc[j][0] += v.x; acc[j][1] += v.y; acc[j][2] += v.z; acc[j][3] += v.w;
            }
            bf* hh = &g_hh[lay][p ^ 1][0][0];  bf* hl = &g_hl[lay][p ^ 1][0][0];
            const bf* qh = &g_hh[lay][p][0][0]; const bf* ql = &g_hl[lay][p][0][0];
            const int r0 = ctam * 32 + wm * 16 + (lane >> 2);
            #pragma unroll
            for (int j = 0; j < 4; j++) {
                int ul = j * 4 + (lane & 3);
                int ug = ctan * 16 + ul;
                float bz = sbias[lay * 32 + 2 * ul], bn = sbias[lay * 32 + 2 * ul + 1];
                #pragma unroll
                for (int rr = 0; rr < 2; rr++) {
                    int r = r0 + rr * 8;
                    float z = 1.f / (1.f + __expf(-(acc[j][rr * 2] + bz)));
                    float e = __expf(2.f * (acc[j][rr * 2 + 1] + bn));
                    float nn = __fdividef(e - 1.f, e + 1.f);
                    float hp = __bfloat162float(qh[r * 1024 + ug]) + __bfloat162float(ql[r * 1024 + ug]);
                    float hv = (1.f - z) * nn + z * hp;
                    bf hi = __float2bfloat16(hv);
                    hh[r * 1024 + ug] = hi;
                    hl[r * 1024 + ug] = __float2bfloat16(hv - __bfloat162float(hi));
                }
            }
        }
        __syncthreads();
    };

    stageF(0, 0, 0, 0); stageF(0, 0, 0, 1); stageF(0, 0, 0, 2);

    for (int t = 0; t < SEQ; t++) {
        // ---- layer 0: 18 chunks; tail prefetches L1 reordered (h1 first) ----
        #pragma unroll
        for (int j = 0; j < 4; j++) acc[j][0]=acc[j][1]=acc[j][2]=acc[j][3]=0.f;
        for (int c = 0; c < 18; c++) {
            cpw_n(pcnt - ccnt - 1);
            __syncthreads();
            int nx = c + 3;
            if (nx < 18) stageF(0, t, p, nx);
            else {
                if (nx == 18) waitf(g_flagsB, genB);   // h1(t-1) ready (free: ~15 chunks of slack)
                stageF(1, t, p, (nx - 18) ^ 16);       // L1 chunks 16,17,18 (h1 part)
            }
            computeC();
        }
        epi(0);
        arrive(g_flagsA, genA);                        // h0_new published
        // ---- layer 1: 32 chunks, order c^16 (h1 half first, h0_new half after wait A) ----
        #pragma unroll
        for (int j = 0; j < 4; j++) acc[j][0]=acc[j][1]=acc[j][2]=acc[j][3]=0.f;
        for (int c = 0; c < 32; c++) {
            cpw_n(pcnt - ccnt - 1);
            __syncthreads();
            int nx = c + 3;
            if (nx < 32) {
                if (nx == 16) waitf(g_flagsA, genA);   // h0_new ready (13 chunks after arrive)
                stageF(1, t, p, nx ^ 16);
            } else if (t + 1 < SEQ) {
                stageF(0, t + 1, p ^ 1, nx - 32);      // next step's layer0 fill
            }
            computeC();
        }
        epi(1);
        arrive(g_flagsB, genB);                        // h1_new published
        p ^= 1;
    }
    waitf(g_flagsB, genB);                             // all h1 final visible

    if (blockIdx.x < 128) {
        const bf* fh = &g_hh[1][p][0][0];
        const bf* fl = &g_hl[1][p][0][0];
        const int row = blockIdx.x;
        float part = 0.f;
        for (int j = tid; j < 1024; j += NTHR)
            part += (__bfloat162float(fh[row * 1024 + j]) + __bfloat162float(fl[row * 1024 + j])) * Wfc[j];
        sred[tid] = part;
        __syncthreads();
        if (tid == 0) {
            float s = 0.f;
            #pragma unroll 8
            for (int i = 0; i < NTHR; i++) s += sred[i];
            out[row] = s + bfc[0];
        }
    }
}

__global__ void ginit(const float* __restrict__ x,
                      const float* __restrict__ b0, const float* __restrict__ b1) {
    long i = (long)blockIdx.x * blockDim.x + threadIdx.x;
    long st = (long)gridDim.x * blockDim.x;
    for (long idx = i; idx < 128L * 65536; idx += st) {
        float v = x[idx];
        bf h = __float2bfloat16(v);
        ((bf*)g_xh)[idx] = h;
        ((bf*)g_xl)[idx] = __float2bfloat16(v - __bfloat162float(h));
    }
    bf z = __float2bfloat16(0.f);
    for (long idx = i; idx < 2L * 2 * 128 * 1024; idx += st) {
        ((bf*)g_hh)[idx] = z; ((bf*)g_hl)[idx] = z;
    }
    if (i < 256 * 32) { g_flagsA[i] = 0u; g_flagsB[i] = 0u; }
    if (i < 4096) {
        int l = (int)(i >> 11), g = (int)(i & 2047);
        int u = g >> 1, col = (g & 1) ? 2048 + u : u;
        g_biasP[l][g] = l ? b1[col] : b0[col];
    }
}

__global__ void prepw(const float* __restrict__ W0, const float* __restrict__ W1) {
    const int l = blockIdx.z;
    const float* W = l ? W1 : W0;
    bf* Dh = l ? &g_w1h[0][0] : &g_w0h[0][0];
    bf* Dl = l ? &g_w1l[0][0] : &g_w0l[0][0];
    const int K = l ? 2048 : 1152;
    const int k0 = blockIdx.x * 32; if (k0 >= K) return;
    const int g0 = blockIdx.y * 32;
    __shared__ float tile[32][33];
    const int tx = threadIdx.x, ty = threadIdx.y;
    {
        int g = g0 + tx, u = g >> 1, col = (g & 1) ? 2048 + u : u;
        #pragma unroll
        for (int r = 0; r < 32; r += 8)
            tile[ty + r][tx] = W[(size_t)(k0 + ty + r) * 3072 + col];
    }
    __syncthreads();
    #pragma unroll
    for (int r = 0; r < 32; r += 8) {
        float v = tile[tx][ty + r];
        bf h = __float2bfloat16(v);
        size_t o = (size_t)(g0 + ty + r) * K + k0 + tx;
        Dh[o] = h;
        Dl[o] = __float2bfloat16(v - __bfloat162float(h));
    }
}

extern "C" void kernel_launch(void* const* d_in, const int* in_sizes, int n_in,
                              void* d_out, int out_size) {
    const float* x   = (const float*)d_in[0];
    const float* W0  = (const float*)d_in[1];
    const float* b0  = (const float*)d_in[2];
    const float* W1  = (const float*)d_in[3];
    const float* b1  = (const float*)d_in[4];
    const float* Wfc = (const float*)d_in[5];
    const float* bfc = (const float*)d_in[6];
    float* out = (float*)d_out;

    cudaFuncSetAttribute(gru_mma, cudaFuncAttributeMaxDynamicSharedMemorySize, SMTOT);
    ginit<<<2048, 256>>>(x, b0, b1);
    prepw<<<dim3(64, 64, 2), dim3(32, 8)>>>(W0, W1);
    gru_mma<<<256, NTHR, SMTOT>>>(Wfc, bfc, out);
}

// round 15
// speedup vs baseline: 1.4717x; 1.1415x over previous
#include <cuda_runtime.h>
#include <cuda_fp16.h>
#include <cstdint>

typedef __half hf;
#define SEQ  512
#define NTHR 128
#define STG  12288                        // A 4K | Whi 4K | Wlo 4K
#define SMTOT (4*STG + 4096 + 256 + 512)
#define SW(o) ((o) ^ (((o) >> 3) & 0x70))

__device__ __align__(1024) hf g_xh[128][65536];
__device__ __align__(1024) hf g_w0h[2048][1152];
__device__ __align__(1024) hf g_w0l[2048][1152];
__device__ __align__(1024) hf g_w1h[2048][2048];
__device__ __align__(1024) hf g_w1l[2048][2048];
__device__ __align__(1024) hf g_hh[2][2][128][1024];   // [layer][ping][row][unit]
__device__ __align__(1024) hf g_hl[2][2][128][1024];
__device__ float    g_biasP[2][2048];
__device__ unsigned g_flagsA[256 * 32];
__device__ unsigned g_flagsB[256 * 32];

__device__ __forceinline__ uint32_t s2u(const void* p) {
    uint32_t a;
    asm("{ .reg .u64 t; cvta.to.shared.u64 t, %1; cvt.u32.u64 %0, t; }" : "=r"(a) : "l"(p));
    return a;
}
__device__ __forceinline__ void cp16(uint32_t dst, const void* src) {
    asm volatile("cp.async.cg.shared.global [%0], [%1], 16;" :: "r"(dst), "l"(src));
}
__device__ __forceinline__ void cpc() { asm volatile("cp.async.commit_group;"); }
__device__ __forceinline__ void cpw_n(int n) {
    if (n <= 0)      asm volatile("cp.async.wait_group 0;");
    else if (n == 1) asm volatile("cp.async.wait_group 1;");
    else             asm volatile("cp.async.wait_group 2;");
}
__device__ __forceinline__ void ldmx4(unsigned* r, uint32_t a) {
    asm volatile("ldmatrix.sync.aligned.m8n8.x4.shared.b16 {%0,%1,%2,%3}, [%4];"
        : "=r"(r[0]), "=r"(r[1]), "=r"(r[2]), "=r"(r[3]) : "r"(a));
}
__device__ __forceinline__ void mma(float* c, const unsigned* a, const unsigned* b) {
    asm volatile("mma.sync.aligned.m16n8k16.row.col.f32.f16.f16.f32 "
        "{%0,%1,%2,%3}, {%4,%5,%6,%7}, {%8,%9}, {%0,%1,%2,%3};"
        : "+f"(c[0]), "+f"(c[1]), "+f"(c[2]), "+f"(c[3])
        : "r"(a[0]), "r"(a[1]), "r"(a[2]), "r"(a[3]), "r"(b[0]), "r"(b[1]));
}
__device__ __forceinline__ void arrive(unsigned* flags, unsigned& gen) {
    gen++;
    if (threadIdx.x == 0)
        asm volatile("st.release.gpu.global.u32 [%0], %1;"
                     :: "l"(&flags[blockIdx.x * 32]), "r"(gen) : "memory");
}
__device__ __forceinline__ void waitf(const unsigned* flags, unsigned gen) {
    const unsigned* f0 = &flags[threadIdx.x * 32];
    const unsigned* f1 = &flags[(threadIdx.x + 128) * 32];
    unsigned v0, v1;
    do {
        asm volatile("ld.acquire.gpu.global.u32 %0, [%1];" : "=r"(v0) : "l"(f0) : "memory");
        asm volatile("ld.acquire.gpu.global.u32 %0, [%1];" : "=r"(v1) : "l"(f1) : "memory");
        if (v0 < gen || v1 < gen) __nanosleep(32);
    } while (v0 < gen || v1 < gen);
    __syncthreads();
}

__global__ void __launch_bounds__(NTHR, 2) gru_mma(
    const float* __restrict__ Wfc, const float* __restrict__ bfc,
    float* __restrict__ out) {
    extern __shared__ __align__(1024) char sm[];
    const uint32_t sb = s2u(sm);
    const int tid = threadIdx.x, warp = tid >> 5, lane = tid & 31;
    const int ctan = blockIdx.x & 63, ctam = blockIdx.x >> 6;   // 64 n x 4 m
    float* redK  = (float*)(sm + 4 * STG);
    float* sbias = (float*)(sm + 4 * STG + 4096);
    float* sred  = sbias + 64;
    if (tid < 64) sbias[tid] = g_biasP[tid >> 5][ctan * 32 + (tid & 31)];
    __syncthreads();

    const int wm = warp & 1;            // m-half (16 rows)
    const int kh = warp >> 1;           // k-half (32 of KC=64)
    const uint32_t aoff  = (wm * 16 + (lane & 15)) * 128 + (lane >> 4) * 16;
    const uint32_t boff0 = (((lane >> 4) & 1) * 8 + (lane & 7)) * 128 + ((lane >> 3) & 1) * 16;
    const uint32_t boff1 = boff0 + 16 * 128;
    unsigned genA = 0, genB = 0; int p = 0;
    int pcnt = 0, ccnt = 0;
    float acc[4][4];

    // L0 chunks: c<2 -> x, else h0_prev. L1: c<16 -> h0_new, else h1_prev.
    auto stageF = [&](int lay, int tt, int pp, int c) {
        const hf* ah; long rstr; int ko;
        if (!lay) {
            if (c < 2) { ah = &g_xh[0][0]; rstr = 65536; ko = tt * 128 + c * 64; }
            else { ah = &g_hh[0][pp][0][0]; rstr = 1024; ko = (c - 2) * 64; }
        } else {
            if (c < 16) { ah = &g_hh[0][pp ^ 1][0][0]; rstr = 1024; ko = c * 64; }
            else { ah = &g_hh[1][pp][0][0]; rstr = 1024; ko = (c - 16) * 64; }
        }
        const hf* wh = lay ? &g_w1h[0][0] : &g_w0h[0][0];
        const hf* wl = lay ? &g_w1l[0][0] : &g_w0l[0][0];
        const long Kst = lay ? 2048 : 1152;
        uint32_t db = sb + (pcnt & 3) * STG;
        #pragma unroll
        for (int it = 0; it < 2; it++) {                       // A: 32r x 8u
            int idx = it * NTHR + tid, r = (idx >> 3) & 31, u = idx & 7;
            cp16(db + SW(r * 128 + u * 16),
                 ah + (long)(ctam * 32 + r) * rstr + ko + u * 8);
        }
        #pragma unroll
        for (int it = 0; it < 4; it++) {                       // W hi/lo: 32r x 8u x 2
            int idx = it * NTHR + tid, d = idx >> 8, r = (idx >> 3) & 31, u = idx & 7;
            cp16(db + 4096 + d * 4096 + SW(r * 128 + u * 16),
                 (d ? wl : wh) + (long)(ctan * 32 + r) * Kst + c * 64 + u * 8);
        }
        cpc(); pcnt++;
    };

    auto computeC = [&]() {
        uint32_t tb = sb + (ccnt & 3) * STG;
        #pragma unroll
        for (int kk = 0; kk < 2; kk++) {
            const uint32_t ko = kh * 64 + kk * 32;
            unsigned a4[4], bh[8], bl[8];
            ldmx4(a4, tb + SW(aoff + ko));
            ldmx4(bh,     tb + 4096 + SW(boff0 + ko));
            ldmx4(bh + 4, tb + 4096 + SW(boff1 + ko));
            ldmx4(bl,     tb + 8192 + SW(boff0 + ko));
            ldmx4(bl + 4, tb + 8192 + SW(boff1 + ko));
            #pragma unroll
            for (int j = 0; j < 4; j++) mma(acc[j], a4, bh + 2 * j);
            #pragma unroll
            for (int j = 0; j < 4; j++) mma(acc[j], a4, bl + 2 * j);
        }
        ccnt++;
    };

    auto epi = [&](int lay) {
        __syncthreads();
        if (kh == 1) {
            float4* rb = (float4*)redK + (wm * 32 + lane) * 4;
            #pragma unroll
            for (int j = 0; j < 4; j++)
                rb[j] = make_float4(acc[j][0], acc[j][1], acc[j][2], acc[j][3]);
        }
        __syncthreads();
        if (kh == 0) {
            const float4* rb = (const float4*)redK + (wm * 32 + lane) * 4;
            #pragma unroll
            for (int j = 0; j < 4; j++) {
                float4 v = rb[j];
                acc[j][0] += v.x; acc[j][1] += v.y; acc[j][2] += v.z; acc[j][3] += v.w;
            }
            hf* hh = &g_hh[lay][p ^ 1][0][0];  hf* hl = &g_hl[lay][p ^ 1][0][0];
            const hf* qh = &g_hh[lay][p][0][0]; const hf* ql = &g_hl[lay][p][0][0];
            const int r0 = ctam * 32 + wm * 16 + (lane >> 2);
            #pragma unroll
            for (int j = 0; j < 4; j++) {
                int ul = j * 4 + (lane & 3);
                int ug = ctan * 16 + ul;
                float bz = sbias[lay * 32 + 2 * ul], bn = sbias[lay * 32 + 2 * ul + 1];
                #pragma unroll
                for (int rr = 0; rr < 2; rr++) {
                    int r = r0 + rr * 8;
                    float z = 1.f / (1.f + __expf(-(acc[j][rr * 2] + bz)));
                    float e = __expf(2.f * (acc[j][rr * 2 + 1] + bn));
                    float nn = __fdividef(e - 1.f, e + 1.f);
                    float hp = __half2float(qh[r * 1024 + ug]) + __half2float(ql[r * 1024 + ug]);
                    float hv = (1.f - z) * nn + z * hp;
                    hf hi = __float2half(hv);
                    hh[r * 1024 + ug] = hi;
                    hl[r * 1024 + ug] = __float2half(hv - __half2float(hi));
                }
            }
        }
        __syncthreads();
    };

    stageF(0, 0, 0, 0); stageF(0, 0, 0, 1); stageF(0, 0, 0, 2);

    for (int t = 0; t < SEQ; t++) {
        // ---- layer 0: 18 chunks; tail prefetches L1 reordered (h1 first) ----
        #pragma unroll
        for (int j = 0; j < 4; j++) acc[j][0]=acc[j][1]=acc[j][2]=acc[j][3]=0.f;
        for (int c = 0; c < 18; c++) {
            cpw_n(pcnt - ccnt - 1);
            __syncthreads();
            int nx = c + 3;
            if (nx < 18) stageF(0, t, p, nx);
            else {
                if (nx == 18) waitf(g_flagsB, genB);   // h1(t-1) ready
                stageF(1, t, p, (nx - 18) ^ 16);       // L1 chunks 16,17,18 (h1 part)
            }
            computeC();
        }
        epi(0);
        arrive(g_flagsA, genA);                        // h0_new published
        // ---- layer 1: 32 chunks, order c^16 ----
        #pragma unroll
        for (int j = 0; j < 4; j++) acc[j][0]=acc[j][1]=acc[j][2]=acc[j][3]=0.f;
        for (int c = 0; c < 32; c++) {
            cpw_n(pcnt - ccnt - 1);
            __syncthreads();
            int nx = c + 3;
            if (nx < 32) {
                if (nx == 16) waitf(g_flagsA, genA);   // h0_new ready
                stageF(1, t, p, nx ^ 16);
            } else if (t + 1 < SEQ) {
                stageF(0, t + 1, p ^ 1, nx - 32);      // next step's layer0 fill
            }
            computeC();
        }
        epi(1);
        arrive(g_flagsB, genB);                        // h1_new published
        p ^= 1;
    }
    waitf(g_flagsB, genB);

    if (blockIdx.x < 128) {
        const hf* fh = &g_hh[1][p][0][0];
        const hf* fl = &g_hl[1][p][0][0];
        const int row = blockIdx.x;
        float part = 0.f;
        for (int j = tid; j < 1024; j += NTHR)
            part += (__half2float(fh[row * 1024 + j]) + __half2float(fl[row * 1024 + j])) * Wfc[j];
        sred[tid] = part;
        __syncthreads();
        if (tid == 0) {
            float s = 0.f;
            #pragma unroll 8
            for (int i = 0; i < NTHR; i++) s += sred[i];
            out[row] = s + bfc[0];
        }
    }
}

__global__ void ginit(const float* __restrict__ x,
                      const float* __restrict__ b0, const float* __restrict__ b1) {
    long i = (long)blockIdx.x * blockDim.x + threadIdx.x;
    long st = (long)gridDim.x * blockDim.x;
    for (long idx = i; idx < 128L * 65536; idx += st)
        ((hf*)g_xh)[idx] = __float2half(x[idx]);
    hf z = __float2half(0.f);
    for (long idx = i; idx < 2L * 2 * 128 * 1024; idx += st) {
        ((hf*)g_hh)[idx] = z; ((hf*)g_hl)[idx] = z;
    }
    if (i < 256 * 32) { g_flagsA[i] = 0u; g_flagsB[i] = 0u; }
    if (i < 4096) {
        int l = (int)(i >> 11), g = (int)(i & 2047);
        int u = g >> 1, col = (g & 1) ? 2048 + u : u;
        g_biasP[l][g] = l ? b1[col] : b0[col];
    }
}

__global__ void prepw(const float* __restrict__ W0, const float* __restrict__ W1) {
    const int l = blockIdx.z;
    const float* W = l ? W1 : W0;
    hf* Dh = l ? &g_w1h[0][0] : &g_w0h[0][0];
    hf* Dl = l ? &g_w1l[0][0] : &g_w0l[0][0];
    const int K = l ? 2048 : 1152;
    const int k0 = blockIdx.x * 32; if (k0 >= K) return;
    const int g0 = blockIdx.y * 32;
    __shared__ float tile[32][33];
    const int tx = threadIdx.x, ty = threadIdx.y;
    {
        int g = g0 + tx, u = g >> 1, col = (g & 1) ? 2048 + u : u;
        #pragma unroll
        for (int r = 0; r < 32; r += 8)
            tile[ty + r][tx] = W[(size_t)(k0 + ty + r) * 3072 + col];
    }
    __syncthreads();
    #pragma unroll
    for (int r = 0; r < 32; r += 8) {
        float v = tile[tx][ty + r];
        hf h = __float2half(v);
        size_t o = (size_t)(g0 + ty + r) * K + k0 + tx;
        Dh[o] = h;
        Dl[o] = __float2half(v - __half2float(h));
    }
}

extern "C" void kernel_launch(void* const* d_in, const int* in_sizes, int n_in,
                              void* d_out, int out_size) {
    const float* x   = (const float*)d_in[0];
    const float* W0  = (const float*)d_in[1];
    const float* b0  = (const float*)d_in[2];
    const float* W1  = (const float*)d_in[3];
    const float* b1  = (const float*)d_in[4];
    const float* Wfc = (const float*)d_in[5];
    const float* bfc = (const float*)d_in[6];
    float* out = (float*)d_out;

    cudaFuncSetAttribute(gru_mma, cudaFuncAttributeMaxDynamicSharedMemorySize, SMTOT);
    ginit<<<2048, 256>>>(x, b0, b1);
    prepw<<<dim3(64, 64, 2), dim3(32, 8)>>>(W0, W1);
    gru_mma<<<256, NTHR, SMTOT>>>(Wfc, bfc, out);
}

// round 17
// speedup vs baseline: 1.5689x; 1.0660x over previous
#include <cuda_runtime.h>
#include <cuda_fp16.h>
#include <cstdint>

typedef __half hf;
#define SEQ  512
#define NTHR 128
#define STG  24576                        // A 8K | Whi 8K | Wlo 8K  (KC=128)
#define SMTOT (4*STG + 4096 + 256 + 512)
#define SW(o) ((o) ^ (((o) >> 3) & 0x70))

__device__ __align__(1024) hf g_xh[128][65536];
__device__ __align__(1024) hf g_w0h[2048][1152];
__device__ __align__(1024) hf g_w0l[2048][1152];
__device__ __align__(1024) hf g_w1h[2048][2048];
__device__ __align__(1024) hf g_w1l[2048][2048];
__device__ __align__(1024) hf g_hh[2][2][128][1024];   // [layer][ping][row][unit]
__device__ __align__(1024) hf g_hl[2][2][128][1024];
__device__ float    g_biasP[2][2048];
__device__ unsigned g_flagsA[256 * 32];
__device__ unsigned g_flagsB[256 * 32];

__device__ __forceinline__ uint32_t s2u(const void* p) {
    uint32_t a;
    asm("{ .reg .u64 t; cvta.to.shared.u64 t, %1; cvt.u32.u64 %0, t; }" : "=r"(a) : "l"(p));
    return a;
}
__device__ __forceinline__ void cp16(uint32_t dst, const void* src) {
    asm volatile("cp.async.cg.shared.global [%0], [%1], 16;" :: "r"(dst), "l"(src));
}
__device__ __forceinline__ void cpc() { asm volatile("cp.async.commit_group;"); }
__device__ __forceinline__ void cpw_n(int n) {
    if (n <= 0)      asm volatile("cp.async.wait_group 0;");
    else if (n == 1) asm volatile("cp.async.wait_group 1;");
    else             asm volatile("cp.async.wait_group 2;");
}
__device__ __forceinline__ void ldmx4(unsigned* r, uint32_t a) {
    asm volatile("ldmatrix.sync.aligned.m8n8.x4.shared.b16 {%0,%1,%2,%3}, [%4];"
        : "=r"(r[0]), "=r"(r[1]), "=r"(r[2]), "=r"(r[3]) : "r"(a));
}
__device__ __forceinline__ void mma(float* c, const unsigned* a, const unsigned* b) {
    asm volatile("mma.sync.aligned.m16n8k16.row.col.f32.f16.f16.f32 "
        "{%0,%1,%2,%3}, {%4,%5,%6,%7}, {%8,%9}, {%0,%1,%2,%3};"
        : "+f"(c[0]), "+f"(c[1]), "+f"(c[2]), "+f"(c[3])
        : "r"(a[0]), "r"(a[1]), "r"(a[2]), "r"(a[3]), "r"(b[0]), "r"(b[1]));
}
__device__ __forceinline__ void arrive(unsigned* flags, unsigned& gen) {
    gen++;
    if (threadIdx.x == 0)
        asm volatile("st.release.gpu.global.u32 [%0], %1;"
                     :: "l"(&flags[blockIdx.x * 32]), "r"(gen) : "memory");
}
__device__ __forceinline__ void waitf(const unsigned* flags, unsigned gen) {
    const unsigned* f0 = &flags[threadIdx.x * 32];
    const unsigned* f1 = &flags[(threadIdx.x + 128) * 32];
    unsigned v0, v1;
    do {
        asm volatile("ld.acquire.gpu.global.u32 %0, [%1];" : "=r"(v0) : "l"(f0) : "memory");
        asm volatile("ld.acquire.gpu.global.u32 %0, [%1];" : "=r"(v1) : "l"(f1) : "memory");
        if (v0 < gen || v1 < gen) __nanosleep(32);
    } while (v0 < gen || v1 < gen);
    __syncthreads();
}

__global__ void __launch_bounds__(NTHR, 2) gru_mma(
    const float* __restrict__ Wfc, const float* __restrict__ bfc,
    float* __restrict__ out) {
    extern __shared__ __align__(1024) char sm[];
    const uint32_t sb = s2u(sm);
    const int tid = threadIdx.x, warp = tid >> 5, lane = tid & 31;
    const int ctan = blockIdx.x & 63, ctam = blockIdx.x >> 6;   // 64 n x 4 m
    float* redK  = (float*)(sm + 4 * STG);
    float* sbias = (float*)(sm + 4 * STG + 4096);
    float* sred  = sbias + 64;
    if (tid < 64) sbias[tid] = g_biasP[tid >> 5][ctan * 32 + (tid & 31)];
    __syncthreads();

    const int wm = warp & 1;            // m-half (16 of 32 rows)
    const int kh = warp >> 1;           // k-half (one k64 sub-tile of KC=128)
    const uint32_t aoff  = (wm * 16 + (lane & 15)) * 128 + (lane >> 4) * 16;
    const uint32_t boff0 = (((lane >> 4) & 1) * 8 + (lane & 7)) * 128 + ((lane >> 3) & 1) * 16;
    const uint32_t boff1 = boff0 + 16 * 128;
    unsigned genA = 0, genB = 0; int p = 0;
    int pcnt = 0, ccnt = 0;
    float acc[4][4];

    // KC=128 chunks. L0 (9): c==0 -> x_t, c>=1 -> h0_prev. L1 (16): c<8 -> h0_new, c>=8 -> h1_prev.
    auto stageF = [&](int lay, int tt, int pp, int c) {
        const hf* ah; long rstr; int ko;
        if (!lay) {
            if (c == 0) { ah = &g_xh[0][0]; rstr = 65536; ko = tt * 128; }
            else { ah = &g_hh[0][pp][0][0]; rstr = 1024; ko = (c - 1) * 128; }
        } else {
            if (c < 8) { ah = &g_hh[0][pp ^ 1][0][0]; rstr = 1024; ko = c * 128; }
            else { ah = &g_hh[1][pp][0][0]; rstr = 1024; ko = (c - 8) * 128; }
        }
        const hf* wh = lay ? &g_w1h[0][0] : &g_w0h[0][0];
        const hf* wl = lay ? &g_w1l[0][0] : &g_w0l[0][0];
        const long Kst = lay ? 2048 : 1152;
        uint32_t db = sb + (pcnt & 3) * STG;
        #pragma unroll
        for (int it = 0; it < 4; it++) {     // A: kb(2) x r(32) x u(8)
            int idx = it * NTHR + tid;
            int kb = idx >> 8, r = (idx >> 3) & 31, u = idx & 7;
            cp16(db + kb * 4096 + SW(r * 128 + u * 16),
                 ah + (long)(ctam * 32 + r) * rstr + ko + kb * 64 + u * 8);
        }
        #pragma unroll
        for (int it = 0; it < 8; it++) {     // W: d(2) x kb(2) x r(32) x u(8)
            int idx = it * NTHR + tid;
            int d = idx >> 9, kb = (idx >> 8) & 1, r = (idx >> 3) & 31, u = idx & 7;
            cp16(db + 8192 + d * 8192 + kb * 4096 + SW(r * 128 + u * 16),
                 (d ? wl : wh) + (long)(ctan * 32 + r) * Kst + c * 128 + kb * 64 + u * 8);
        }
        cpc(); pcnt++;
    };

    auto computeC = [&]() {
        uint32_t tb = sb + (ccnt & 3) * STG;
        const uint32_t ka = tb + kh * 4096;
        const uint32_t kb = tb + 8192 + kh * 4096;
        const uint32_t kl = tb + 16384 + kh * 4096;
        #pragma unroll
        for (int kk = 0; kk < 4; kk++) {                 // FIX: 4 x k16 = full k64 sub-tile
            const uint32_t ko = kk * 32;
            unsigned a4[4], bh[8], bl[8];
            ldmx4(a4, ka + SW(aoff + ko));
            ldmx4(bh,     kb + SW(boff0 + ko));
            ldmx4(bh + 4, kb + SW(boff1 + ko));
            ldmx4(bl,     kl + SW(boff0 + ko));
            ldmx4(bl + 4, kl + SW(boff1 + ko));
            #pragma unroll
            for (int j = 0; j < 4; j++) mma(acc[j], a4, bh + 2 * j);
            #pragma unroll
            for (int j = 0; j < 4; j++) mma(acc[j], a4, bl + 2 * j);
        }
        ccnt++;
    };

    auto epi = [&](int lay) {
        __syncthreads();
        if (kh == 1) {
            float4* rb = (float4*)redK + (wm * 32 + lane) * 4;
            #pragma unroll
            for (int j = 0; j < 4; j++)
                rb[j] = make_float4(acc[j][0], acc[j][1], acc[j][2], acc[j][3]);
        }
        __syncthreads();
        if (kh == 0) {
            const float4* rb = (const float4*)redK + (wm * 32 + lane) * 4;
            #pragma unroll
            for (int j = 0; j < 4; j++) {
                float4 v = rb[j];
                acc[j][0] += v.x; acc[j][1] += v.y; acc[j][2] += v.z; acc[j][3] += v.w;
            }
            hf* hh = &g_hh[lay][p ^ 1][0][0];  hf* hl = &g_hl[lay][p ^ 1][0][0];
            const hf* qh = &g_hh[lay][p][0][0]; const hf* ql = &g_hl[lay][p][0][0];
            const int r0 = ctam * 32 + wm * 16 + (lane >> 2);
            #pragma unroll
            for (int j = 0; j < 4; j++) {
                int ul = j * 4 + (lane & 3);
                int ug = ctan * 16 + ul;
                float bz = sbias[lay * 32 + 2 * ul], bn = sbias[lay * 32 + 2 * ul + 1];
                #pragma unroll
                for (int rr = 0; rr < 2; rr++) {
                    int r = r0 + rr * 8;
                    float z = 1.f / (1.f + __expf(-(acc[j][rr * 2] + bz)));
                    float e = __expf(2.f * (acc[j][rr * 2 + 1] + bn));
                    float nn = __fdividef(e - 1.f, e + 1.f);
                    float hp = __half2float(qh[r * 1024 + ug]) + __half2float(ql[r * 1024 + ug]);
                    float hv = (1.f - z) * nn + z * hp;
                    hf hi = __float2half(hv);
                    hh[r * 1024 + ug] = hi;
                    hl[r * 1024 + ug] = __float2half(hv - __half2float(hi));
                }
            }
        }
        __syncthreads();
    };

    stageF(0, 0, 0, 0); stageF(0, 0, 0, 1); stageF(0, 0, 0, 2);

    for (int t = 0; t < SEQ; t++) {
        // ---- layer 0: 9 chunks; tail prefetches L1 reordered (h1 half first) ----
        #pragma unroll
        for (int j = 0; j < 4; j++) acc[j][0]=acc[j][1]=acc[j][2]=acc[j][3]=0.f;
        for (int c = 0; c < 9; c++) {
            cpw_n(pcnt - ccnt - 1);
            __syncthreads();
            int nx = c + 3;
            if (nx < 9) stageF(0, t, p, nx);
            else {
                if (nx == 9) waitf(g_flagsB, genB);     // h1(t-1) ready
                stageF(1, t, p, (nx - 9) ^ 8);          // L1 chunks 8,9,10 (h1 part)
            }
            computeC();
        }
        epi(0);
        arrive(g_flagsA, genA);                         // h0_new published
        // ---- layer 1: 16 chunks, order c^8 (h1 half first, h0_new half after wait A) ----
        #pragma unroll
        for (int j = 0; j < 4; j++) acc[j][0]=acc[j][1]=acc[j][2]=acc[j][3]=0.f;
        for (int c = 0; c < 16; c++) {
            cpw_n(pcnt - ccnt - 1);
            __syncthreads();
            int nx = c + 3;
            if (nx < 16) {
                if (nx == 8) waitf(g_flagsA, genA);     // h0_new ready
                stageF(1, t, p, nx ^ 8);
            } else if (t + 1 < SEQ) {
                stageF(0, t + 1, p ^ 1, nx - 16);       // next step's layer0 fill
            }
            computeC();
        }
        epi(1);
        arrive(g_flagsB, genB);                         // h1_new published
        p ^= 1;
    }
    waitf(g_flagsB, genB);

    if (blockIdx.x < 128) {
        const hf* fh = &g_hh[1][p][0][0];
        const hf* fl = &g_hl[1][p][0][0];
        const int row = blockIdx.x;
        float part = 0.f;
        for (int j = tid; j < 1024; j += NTHR)
            part += (__half2float(fh[row * 1024 + j]) + __half2float(fl[row * 1024 + j])) * Wfc[j];
        sred[tid] = part;
        __syncthreads();
        if (tid == 0) {
            float s = 0.f;
            #pragma unroll 8
            for (int i = 0; i < NTHR; i++) s += sred[i];
            out[row] = s + bfc[0];
        }
    }
}

__global__ void ginit(const float* __restrict__ x,
                      const float* __restrict__ b0, const float* __restrict__ b1) {
    long i = (long)blockIdx.x * blockDim.x + threadIdx.x;
    long st = (long)gridDim.x * blockDim.x;
    for (long idx = i; idx < 128L * 65536; idx += st)
        ((hf*)g_xh)[idx] = __float2half(x[idx]);
    hf z = __float2half(0.f);
    for (long idx = i; idx < 2L * 2 * 128 * 1024; idx += st) {
        ((hf*)g_hh)[idx] = z; ((hf*)g_hl)[idx] = z;
    }
    if (i < 256 * 32) { g_flagsA[i] = 0u; g_flagsB[i] = 0u; }
    if (i < 4096) {
        int l = (int)(i >> 11), g = (int)(i & 2047);
        int u = g >> 1, col = (g & 1) ? 2048 + u : u;
        g_biasP[l][g] = l ? b1[col] : b0[col];
    }
}

__global__ void prepw(const float* __restrict__ W0, const float* __restrict__ W1) {
    const int l = blockIdx.z;
    const float* W = l ? W1 : W0;
    hf* Dh = l ? &g_w1h[0][0] : &g_w0h[0][0];
    hf* Dl = l ? &g_w1l[0][0] : &g_w0l[0][0];
    const int K = l ? 2048 : 1152;
    const int k0 = blockIdx.x * 32; if (k0 >= K) return;
    const int g0 = blockIdx.y * 32;
    __shared__ float tile[32][33];
    const int tx = threadIdx.x, ty = threadIdx.y;
    {
        int g = g0 + tx, u = g >> 1, col = (g & 1) ? 2048 + u : u;
        #pragma unroll
        for (int r = 0; r < 32; r += 8)
            tile[ty + r][tx] = W[(size_t)(k0 + ty + r) * 3072 + col];
    }
    __syncthreads();
    #pragma unroll
    for (int r = 0; r < 32; r += 8) {
        float v = tile[tx][ty + r];
        hf h = __float2half(v);
        size_t o = (size_t)(g0 + ty + r) * K + k0 + tx;
        Dh[o] = h;
        Dl[o] = __float2half(v - __half2float(h));
    }
}

extern "C" void kernel_launch(void* const* d_in, const int* in_sizes, int n_in,
                              void* d_out, int out_size) {
    const float* x   = (const float*)d_in[0];
    const float* W0  = (const float*)d_in[1];
    const float* b0  = (const float*)d_in[2];
    const float* W1  = (const float*)d_in[3];
    const float* b1  = (const float*)d_in[4];
    const float* Wfc = (const float*)d_in[5];
    const float* bfc = (const float*)d_in[6];
    float* out = (float*)d_out;

    cudaFuncSetAttribute(gru_mma, cudaFuncAttributeMaxDynamicSharedMemorySize, SMTOT);
    ginit<<<2048, 256>>>(x, b0, b1);
    prepw<<<dim3(64, 64, 2), dim3(32, 8)>>>(W0, W1);
    gru_mma<<<256, NTHR, SMTOT>>>(Wfc, bfc, out);
}